// round 11
// baseline (speedup 1.0000x reference)
#include <cuda_runtime.h>
#include <cuda_fp16.h>
#include <cstdint>

// ---------------------------------------------------------------------------
// Swin WindowAttention, sm_103 base ISA.
//   GEMMs: fp16 mma.sync m16n8k16, BM=128 BN=128 BK=64, 4 warps each 64x64.
//   Attention: HMMA, 2 heads per CTA (256 thr), bias/mask prefetched into
//   registers at kernel start; QK 2-pass (K hi/lo), AV 1-pass.
// ---------------------------------------------------------------------------

#define N_WIN 4096
#define L_TOK 49
#define CH    256
#define NHEAD 8
#define DK    32
#define M_ROWS (N_WIN * L_TOK)   // 200704
#define BMROW 52
#define BMWIN 2560

__device__ __half g_xh[(size_t)M_ROWS * CH];
__device__ __half g_qh[(size_t)M_ROWS * 768];
__device__ __half g_ql[(size_t)M_ROWS * 768];
__device__ __half g_ah[(size_t)M_ROWS * CH];
__device__ __half g_wqkv[256 * 768];
__device__ __half g_wo[256 * 256];
__device__ float  g_bm[512 * BMWIN];

// ------------------------------ helpers ------------------------------------

__device__ __forceinline__ uint32_t smem_u32(const void* p) {
    uint32_t a;
    asm("{ .reg .u64 t; cvta.to.shared.u64 t, %1; cvt.u32.u64 %0, t; }"
        : "=r"(a) : "l"(p));
    return a;
}
__device__ __forceinline__ void cp16(uint32_t dst, const void* src) {
    asm volatile("cp.async.cg.shared.global [%0], [%1], 16;"
                 :: "r"(dst), "l"(src));
}
#define CP_COMMIT() asm volatile("cp.async.commit_group;" ::: "memory")
#define CP_WAIT1()  asm volatile("cp.async.wait_group 1;" ::: "memory")
#define CP_WAIT0()  asm volatile("cp.async.wait_group 0;" ::: "memory")

__device__ __forceinline__ void ldsm_x4(uint32_t addr, uint32_t* r) {
    asm volatile("ldmatrix.sync.aligned.m8n8.x4.shared.b16 {%0,%1,%2,%3}, [%4];"
                 : "=r"(r[0]), "=r"(r[1]), "=r"(r[2]), "=r"(r[3]) : "r"(addr));
}
__device__ __forceinline__ void ldsm_x4_t(uint32_t addr, uint32_t* r) {
    asm volatile("ldmatrix.sync.aligned.m8n8.x4.trans.shared.b16 {%0,%1,%2,%3}, [%4];"
                 : "=r"(r[0]), "=r"(r[1]), "=r"(r[2]), "=r"(r[3]) : "r"(addr));
}
__device__ __forceinline__ void mma16816(float* c, const uint32_t* a,
                                         const uint32_t* b) {
    asm volatile(
        "mma.sync.aligned.m16n8k16.row.col.f32.f16.f16.f32 "
        "{%0,%1,%2,%3}, {%4,%5,%6,%7}, {%8,%9}, {%0,%1,%2,%3};"
        : "+f"(c[0]), "+f"(c[1]), "+f"(c[2]), "+f"(c[3])
        : "r"(a[0]), "r"(a[1]), "r"(a[2]), "r"(a[3]), "r"(b[0]), "r"(b[1]));
}
__device__ __forceinline__ uint32_t pack_h2(float x, float y) {
    __half2 v = __halves2half2(__float2half_rn(x), __float2half_rn(y));
    return *(uint32_t*)&v;
}

// ------------------------------ prep kernels --------------------------------

__global__ void k_split_x(const float* __restrict__ x) {
    int i = blockIdx.x * blockDim.x + threadIdx.x;
    if (i >= (M_ROWS * CH) / 4) return;
    float4 v = ((const float4*)x)[i];
    ((__half2*)g_xh)[i * 2] =
        __halves2half2(__float2half_rn(v.x), __float2half_rn(v.y));
    ((__half2*)g_xh)[i * 2 + 1] =
        __halves2half2(__float2half_rn(v.z), __float2half_rn(v.w));
}

__global__ void k_split_w(const float* __restrict__ wq,
                          const float* __restrict__ wk,
                          const float* __restrict__ wv,
                          const float* __restrict__ wo) {
    int gid = blockIdx.x * blockDim.x + threadIdx.x;
    if (gid >= 65536) return;
    int sect = gid >> 14;
    int i    = gid & 16383;
    const float* src = (sect == 0) ? wq : (sect == 1) ? wk
                     : (sect == 2) ? wv : wo;
    float4 v = ((const float4*)src)[i];
    __half2 a = __halves2half2(__float2half_rn(v.x), __float2half_rn(v.y));
    __half2 b = __halves2half2(__float2half_rn(v.z), __float2half_rn(v.w));
    int k = (i * 4) >> 8;
    int n = (i * 4) & 255;
    if (sect < 3) {
        __half2* d = (__half2*)&g_wqkv[(size_t)k * 768 + sect * 256 + n];
        d[0] = a; d[1] = b;
    } else {
        __half2* d = (__half2*)&g_wo[(size_t)k * 256 + n];
        d[0] = a; d[1] = b;
    }
}

__global__ void k_bm(const float* __restrict__ mask,
                     const float* __restrict__ bias_table,
                     const int* __restrict__ rel_index) {
    const int bid = blockIdx.x;
    const int w   = bid >> 3;
    const int h   = bid & 7;
    float* dst = g_bm + (size_t)bid * BMWIN;
    const float* mrow = mask + (size_t)w * (L_TOK * L_TOK);
    for (int i = threadIdx.x; i < L_TOK * L_TOK; i += blockDim.x)
        dst[(i / L_TOK) * BMROW + (i % L_TOK)] =
            bias_table[rel_index[i] * NHEAD + h] + mrow[i];
}

// ------------------------------ GEMM ----------------------------------------
// BM=128 BN=128 BK=64, 4 warps (2m x 2n), warp tile 64x64. (unchanged)

#define AROWH 72
#define BROWH 136
#define O_A 0
#define O_B 18432
#define S_BUF 35840
#define SMEM_BYTES (2 * S_BUF)
#define CS 136

__global__ __launch_bounds__(128, 2)
void k_hgemm(const __half* __restrict__ Ah, const __half* __restrict__ Wh,
             int ldW, float* __restrict__ Cf, int ldC, int mode)
{
    extern __shared__ char smem[];
    const uint32_t sb = smem_u32(smem);
    const int tid  = threadIdx.x;
    const int lane = tid & 31;
    const int wid  = tid >> 5;
    const int warp_m = wid & 1;
    const int warp_n = wid >> 1;
    const int rowBlock = blockIdx.y * 128;
    const int col0     = blockIdx.x * 128;

    float acc[4][8][4];
#pragma unroll
    for (int mt = 0; mt < 4; mt++)
#pragma unroll
        for (int nt = 0; nt < 8; nt++)
#pragma unroll
            for (int i = 0; i < 4; i++) acc[mt][nt][i] = 0.f;

    auto issue = [&](int c, int buf) {
        uint32_t s = sb + buf * S_BUF;
#pragma unroll
        for (int q8 = 0; q8 < 8; q8++) {
            int q   = tid + 128 * q8;
            int row = q >> 3;
            int seg = (q & 7) * 8;
            cp16(s + O_A + row * (AROWH * 2) + seg * 2,
                 Ah + (size_t)(rowBlock + row) * CH + c * 64 + seg);
        }
#pragma unroll
        for (int q8 = 0; q8 < 8; q8++) {
            int q   = tid + 128 * q8;
            int k   = q >> 4;
            int seg = (q & 15) * 8;
            cp16(s + O_B + k * (BROWH * 2) + seg * 2,
                 Wh + (size_t)(c * 64 + k) * ldW + col0 + seg);
        }
        CP_COMMIT();
    };

    const int arow_l = warp_m * 64 + (lane & 15);
    const int acol_l = (lane >> 4) * 8;
    const int brow_l = (lane & 7) + ((lane >> 3) & 1) * 8;
    const int bcol_l = warp_n * 64 + (lane >> 4) * 8;

    issue(0, 0);

#pragma unroll 1
    for (int c = 0; c < 4; c++) {
        if (c < 3) { issue(c + 1, (c + 1) & 1); CP_WAIT1(); }
        else       { CP_WAIT0(); }
        __syncthreads();

        const uint32_t s = sb + (c & 1) * S_BUF;
#pragma unroll
        for (int ks = 0; ks < 4; ks++) {
            uint32_t a[4][4], b[4][4];
            const uint32_t aoff = (acol_l + ks * 16) * 2;
#pragma unroll
            for (int mt = 0; mt < 4; mt++)
                ldsm_x4(s + O_A + (arow_l + mt * 16) * (AROWH * 2) + aoff,
                        a[mt]);
            const uint32_t brow = (brow_l + ks * 16) * (BROWH * 2);
#pragma unroll
            for (int np = 0; np < 4; np++)
                ldsm_x4_t(s + O_B + brow + (bcol_l + np * 16) * 2, b[np]);
#pragma unroll
            for (int mt = 0; mt < 4; mt++)
#pragma unroll
                for (int nt = 0; nt < 8; nt++)
                    mma16816(acc[mt][nt], a[mt], &b[nt >> 1][(nt & 1) * 2]);
        }
        __syncthreads();
    }

    float* cs = (float*)smem;
    const int g  = lane >> 2;
    const int tc = (lane & 3) * 2;
#pragma unroll
    for (int mt = 0; mt < 4; mt++) {
        const int r = warp_m * 64 + mt * 16 + g;
#pragma unroll
        for (int nt = 0; nt < 8; nt++) {
            const int cc = warp_n * 64 + nt * 8 + tc;
            *(float2*)&cs[r * CS + cc] =
                make_float2(acc[mt][nt][0], acc[mt][nt][1]);
            *(float2*)&cs[(r + 8) * CS + cc] =
                make_float2(acc[mt][nt][2], acc[mt][nt][3]);
        }
    }
    __syncthreads();

    const bool wlo = (col0 >= 256) && (col0 < 512);
#pragma unroll
    for (int i = 0; i < 16; i++) {
        const int id  = tid + 128 * i;
        const int row = id >> 4;
        const int col = (id & 15) * 8;
        float4 v0 = *(float4*)&cs[row * CS + col];
        float4 v1 = *(float4*)&cs[row * CS + col + 4];
        if (mode == 0) {
            uint4 hi;
            hi.x = pack_h2(v0.x, v0.y); hi.y = pack_h2(v0.z, v0.w);
            hi.z = pack_h2(v1.x, v1.y); hi.w = pack_h2(v1.z, v1.w);
            size_t o = (size_t)(rowBlock + row) * 768 + col0 + col;
            *(uint4*)&g_qh[o] = hi;
            if (wlo) {
                __half2* hp = (__half2*)&hi;
                uint4 lo;
                lo.x = pack_h2(v0.x - __low2float(hp[0]),
                               v0.y - __high2float(hp[0]));
                lo.y = pack_h2(v0.z - __low2float(hp[1]),
                               v0.w - __high2float(hp[1]));
                lo.z = pack_h2(v1.x - __low2float(hp[2]),
                               v1.y - __high2float(hp[2]));
                lo.w = pack_h2(v1.z - __low2float(hp[3]),
                               v1.w - __high2float(hp[3]));
                *(uint4*)&g_ql[o] = lo;
            }
        } else {
            size_t o = (size_t)(rowBlock + row) * ldC + col0 + col;
            *(float4*)&Cf[o]     = v0;
            *(float4*)&Cf[o + 4] = v1;
        }
    }
}

// ------------------------------ attention (HMMA) ----------------------------
// 2 heads per CTA: warps 0-3 -> head 2*hp, warps 4-7 -> head 2*hp+1.
// Bias+mask prefetched into registers at kernel start.

#define KSTR 40

__global__ __launch_bounds__(256)
void attn_kernel()
{
    __shared__ __align__(16) __half sQ [2][64 * KSTR];
    __shared__ __align__(16) __half sKh[2][64 * KSTR];
    __shared__ __align__(16) __half sKl[2][64 * KSTR];
    __shared__ __align__(16) __half sVh[2][64 * KSTR];

    const int bid = blockIdx.x;
    const int hp  = bid & 3;
    const int n   = bid >> 2;
    const int tid = threadIdx.x;
    const int wg   = tid >> 7;          // 0/1 -> head hp*2+wg
    const int warp = (tid >> 5) & 3;    // warp within group
    const int lane = tid & 31;
    const int g    = lane >> 2;
    const int t    = lane & 3;
    const int h    = hp * 2 + wg;

    // ---- bias+mask prefetch (no smem dependence; hides L2 latency) ----
    const int r0 = warp * 16 + g;
    const int r1 = r0 + 8;
    const float* bm = g_bm + (size_t)(((n & 63) << 3) | h) * BMWIN;
    const int r0e = (r0 < L_TOK ? r0 : L_TOK - 1) * BMROW;
    const int r1e = (r1 < L_TOK ? r1 : L_TOK - 1) * BMROW;
    float2 bf0[8], bf1[8];
#pragma unroll
    for (int nt = 0; nt < 8; nt++) {
        const int j0 = nt * 8 + t * 2;   // <= 62 < BMWIN bound for row 48
        bf0[nt] = __ldg((const float2*)&bm[r0e + j0]);
        bf1[nt] = __ldg((const float2*)&bm[r1e + j0]);
    }

    // ---- zero V pad rows, load Q/Kh/Kl/Vh for both heads (128B rows) ----
    for (int idx = tid; idx < 120; idx += 256) {
        int hh = idx >= 60;
        int r  = 49 + ((idx % 60) >> 2);
        int q4 = idx & 3;
        *(int4*)(sVh[hh] + r * KSTR + q4 * 8) = make_int4(0, 0, 0, 0);
    }
    {
        const size_t rb = (size_t)n * L_TOK * 768 + hp * 64;
        for (int idx = tid; idx < 4 * 392; idx += 256) {
            int p   = idx / 392;
            int rem = idx - p * 392;
            int r   = rem >> 3;
            int j   = rem & 7;           // int4 within 128B two-head row
            int hh  = j >> 2;
            int q4  = j & 3;
            const __half* src;
            __half* dst;
            switch (p) {
                case 0: src = g_qh + rb;       dst = sQ[hh];  break;
                case 1: src = g_qh + rb + 256; dst = sKh[hh]; break;
                case 2: src = g_ql + rb + 256; dst = sKl[hh]; break;
                default: src = g_qh + rb + 512; dst = sVh[hh]; break;
            }
            *(int4*)(dst + r * KSTR + q4 * 8) =
                *(const int4*)(src + (size_t)r * 768 + j * 8);
        }
    }
    __syncthreads();

    // ---- QK ----
    const uint32_t bq  = smem_u32(sQ[wg]);
    const uint32_t bkh = smem_u32(sKh[wg]);
    const uint32_t bkl = smem_u32(sKl[wg]);
    const int aRow = warp * 16 + (lane & 15);
    const int aCol = (lane >> 4) * 8;

    uint32_t qa[2][4];
    ldsm_x4(bq + (aRow * KSTR + aCol) * 2, qa[0]);
    ldsm_x4(bq + (aRow * KSTR + aCol + 16) * 2, qa[1]);

    float c[8][4];
#pragma unroll
    for (int nt = 0; nt < 8; nt++)
#pragma unroll
        for (int i = 0; i < 4; i++) c[nt][i] = 0.f;

#pragma unroll
    for (int pass = 0; pass < 2; pass++) {
        const uint32_t base = pass ? bkl : bkh;
#pragma unroll
        for (int kt = 0; kt < 2; kt++) {
#pragma unroll
            for (int jp = 0; jp < 4; jp++) {
                uint32_t kb[4];
                ldsm_x4(base + ((jp * 16 + (lane & 15)) * KSTR +
                                (lane >> 4) * 8 + kt * 16) * 2, kb);
                uint32_t b0[2] = {kb[0], kb[2]};
                uint32_t b1[2] = {kb[1], kb[3]};
                mma16816(c[jp * 2],     qa[kt], b0);
                mma16816(c[jp * 2 + 1], qa[kt], b1);
            }
        }
    }

    // ---- bias+mask from prefetched regs, softmax ----
#pragma unroll
    for (int nt = 0; nt < 8; nt++) {
        const int j0 = nt * 8 + t * 2;
        if (j0 < L_TOK) {
            c[nt][0] += bf0[nt].x;
            c[nt][2] += bf1[nt].x;
            if (j0 + 1 < L_TOK) { c[nt][1] += bf0[nt].y; c[nt][3] += bf1[nt].y; }
            else { c[nt][1] = -3.0e38f; c[nt][3] = -3.0e38f; }
        } else {
            c[nt][0] = c[nt][1] = c[nt][2] = c[nt][3] = -3.0e38f;
        }
    }

    float mx0 = -3.0e38f, mx1 = -3.0e38f;
#pragma unroll
    for (int nt = 0; nt < 8; nt++) {
        mx0 = fmaxf(mx0, fmaxf(c[nt][0], c[nt][1]));
        mx1 = fmaxf(mx1, fmaxf(c[nt][2], c[nt][3]));
    }
    mx0 = fmaxf(mx0, __shfl_xor_sync(0xffffffffu, mx0, 1));
    mx0 = fmaxf(mx0, __shfl_xor_sync(0xffffffffu, mx0, 2));
    mx1 = fmaxf(mx1, __shfl_xor_sync(0xffffffffu, mx1, 1));
    mx1 = fmaxf(mx1, __shfl_xor_sync(0xffffffffu, mx1, 2));

    float s0 = 0.f, s1 = 0.f;
#pragma unroll
    for (int nt = 0; nt < 8; nt++) {
        c[nt][0] = __expf(c[nt][0] - mx0); s0 += c[nt][0];
        c[nt][1] = __expf(c[nt][1] - mx0); s0 += c[nt][1];
        c[nt][2] = __expf(c[nt][2] - mx1); s1 += c[nt][2];
        c[nt][3] = __expf(c[nt][3] - mx1); s1 += c[nt][3];
    }
    s0 += __shfl_xor_sync(0xffffffffu, s0, 1);
    s0 += __shfl_xor_sync(0xffffffffu, s0, 2);
    s1 += __shfl_xor_sync(0xffffffffu, s1, 1);
    s1 += __shfl_xor_sync(0xffffffffu, s1, 2);
    const float rs0 = 1.f / s0;
    const float rs1 = 1.f / s1;

    // ---- AV ----
    const uint32_t bvh = smem_u32(sVh[wg]);
    const int vRow = (lane & 7) + ((lane >> 3) & 1) * 8;
    const int vCol = (lane >> 4) * 8;

    float o[4][4];
#pragma unroll
    for (int nt = 0; nt < 4; nt++)
#pragma unroll
        for (int i = 0; i < 4; i++) o[nt][i] = 0.f;

#pragma unroll
    for (int kt = 0; kt < 4; kt++) {
        uint32_t ph[4];
#pragma unroll
        for (int q = 0; q < 2; q++) {
            const float* cc = c[2 * kt + q];
            ph[q * 2]     = pack_h2(cc[0], cc[1]);
            ph[q * 2 + 1] = pack_h2(cc[2], cc[3]);
        }
        uint32_t vh[2][4];
        const uint32_t roff = (kt * 16 + vRow) * KSTR;
        ldsm_x4_t(bvh + (roff + vCol) * 2,      vh[0]);
        ldsm_x4_t(bvh + (roff + vCol + 16) * 2, vh[1]);
#pragma unroll
        for (int nt = 0; nt < 4; nt++)
            mma16816(o[nt], ph, &vh[nt >> 1][(nt & 1) * 2]);
    }

    if (r0 < L_TOK) {
        __half* orow = g_ah + (size_t)(n * L_TOK + r0) * CH + h * DK;
#pragma unroll
        for (int nt = 0; nt < 4; nt++)
            *(__half2*)&orow[nt * 8 + t * 2] =
                __halves2half2(__float2half_rn(o[nt][0] * rs0),
                               __float2half_rn(o[nt][1] * rs0));
    }
    if (r1 < L_TOK) {
        __half* orow = g_ah + (size_t)(n * L_TOK + r1) * CH + h * DK;
#pragma unroll
        for (int nt = 0; nt < 4; nt++)
            *(__half2*)&orow[nt * 8 + t * 2] =
                __halves2half2(__float2half_rn(o[nt][2] * rs1),
                               __float2half_rn(o[nt][3] * rs1));
    }
}

// ------------------------------- launch --------------------------------------

extern "C" void kernel_launch(void* const* d_in, const int* in_sizes, int n_in,
                              void* d_out, int out_size)
{
    (void)in_sizes; (void)n_in; (void)out_size;
    const float* x    = (const float*)d_in[0];
    const float* mask = (const float*)d_in[1];
    const float* wq   = (const float*)d_in[2];
    const float* wk   = (const float*)d_in[3];
    const float* wv   = (const float*)d_in[4];
    const float* wo   = (const float*)d_in[5];
    const float* bias = (const float*)d_in[6];
    const int*   rel  = (const int*)d_in[7];
    float* out = (float*)d_out;

    static __half *xh = nullptr, *ah = nullptr, *wqkv = nullptr, *woh = nullptr;
    if (!xh) {
        cudaGetSymbolAddress((void**)&xh,   g_xh);
        cudaGetSymbolAddress((void**)&ah,   g_ah);
        cudaGetSymbolAddress((void**)&wqkv, g_wqkv);
        cudaGetSymbolAddress((void**)&woh,  g_wo);
        cudaFuncSetAttribute(k_hgemm,
                             cudaFuncAttributeMaxDynamicSharedMemorySize,
                             SMEM_BYTES);
    }

    k_split_x<<<(M_ROWS * CH / 4 + 255) / 256, 256>>>(x);
    k_split_w<<<256, 256>>>(wq, wk, wv, wo);
    k_bm<<<512, 256>>>(mask, bias, rel);
    k_hgemm<<<dim3(6, M_ROWS / 128), 128, SMEM_BYTES>>>(xh, wqkv, 768,
                                                        nullptr, 768, 0);
    attn_kernel<<<N_WIN * 4, 256>>>();
    k_hgemm<<<dim3(2, M_ROWS / 128), 128, SMEM_BYTES>>>(ah, woh, 256,
                                                        out, 256, 1);
}

// round 12
// speedup vs baseline: 1.1652x; 1.1652x over previous
#include <cuda_runtime.h>
#include <cuda_fp16.h>
#include <cstdint>

// ---------------------------------------------------------------------------
// Swin WindowAttention, sm_103 base ISA.
//   GEMMs: fp16 mma.sync m16n8k16, BM=128 BN=128 BK=64, 4 warps each 64x64.
//   Attention: HMMA per (window,head): QK 1-pass, AV 1-pass (all-fp16
//   operands, fp32 accum); bias+mask loaded directly from L2.
// ---------------------------------------------------------------------------

#define N_WIN 4096
#define L_TOK 49
#define CH    256
#define NHEAD 8
#define DK    32
#define M_ROWS (N_WIN * L_TOK)   // 200704
#define BMROW 52
#define BMWIN 2560

__device__ __half g_xh[(size_t)M_ROWS * CH];
__device__ __half g_qh[(size_t)M_ROWS * 768];
__device__ __half g_ah[(size_t)M_ROWS * CH];
__device__ __half g_wqkv[256 * 768];
__device__ __half g_wo[256 * 256];
__device__ float  g_bm[512 * BMWIN];

// ------------------------------ helpers ------------------------------------

__device__ __forceinline__ uint32_t smem_u32(const void* p) {
    uint32_t a;
    asm("{ .reg .u64 t; cvta.to.shared.u64 t, %1; cvt.u32.u64 %0, t; }"
        : "=r"(a) : "l"(p));
    return a;
}
__device__ __forceinline__ void cp16(uint32_t dst, const void* src) {
    asm volatile("cp.async.cg.shared.global [%0], [%1], 16;"
                 :: "r"(dst), "l"(src));
}
#define CP_COMMIT() asm volatile("cp.async.commit_group;" ::: "memory")
#define CP_WAIT1()  asm volatile("cp.async.wait_group 1;" ::: "memory")
#define CP_WAIT0()  asm volatile("cp.async.wait_group 0;" ::: "memory")

__device__ __forceinline__ void ldsm_x4(uint32_t addr, uint32_t* r) {
    asm volatile("ldmatrix.sync.aligned.m8n8.x4.shared.b16 {%0,%1,%2,%3}, [%4];"
                 : "=r"(r[0]), "=r"(r[1]), "=r"(r[2]), "=r"(r[3]) : "r"(addr));
}
__device__ __forceinline__ void ldsm_x4_t(uint32_t addr, uint32_t* r) {
    asm volatile("ldmatrix.sync.aligned.m8n8.x4.trans.shared.b16 {%0,%1,%2,%3}, [%4];"
                 : "=r"(r[0]), "=r"(r[1]), "=r"(r[2]), "=r"(r[3]) : "r"(addr));
}
__device__ __forceinline__ void mma16816(float* c, const uint32_t* a,
                                         const uint32_t* b) {
    asm volatile(
        "mma.sync.aligned.m16n8k16.row.col.f32.f16.f16.f32 "
        "{%0,%1,%2,%3}, {%4,%5,%6,%7}, {%8,%9}, {%0,%1,%2,%3};"
        : "+f"(c[0]), "+f"(c[1]), "+f"(c[2]), "+f"(c[3])
        : "r"(a[0]), "r"(a[1]), "r"(a[2]), "r"(a[3]), "r"(b[0]), "r"(b[1]));
}
__device__ __forceinline__ uint32_t pack_h2(float x, float y) {
    __half2 v = __halves2half2(__float2half_rn(x), __float2half_rn(y));
    return *(uint32_t*)&v;
}

// ------------------------------ prep kernels --------------------------------

__global__ void k_split_x(const float* __restrict__ x) {
    int i = blockIdx.x * blockDim.x + threadIdx.x;
    if (i >= (M_ROWS * CH) / 4) return;
    float4 v = ((const float4*)x)[i];
    ((__half2*)g_xh)[i * 2] =
        __halves2half2(__float2half_rn(v.x), __float2half_rn(v.y));
    ((__half2*)g_xh)[i * 2 + 1] =
        __halves2half2(__float2half_rn(v.z), __float2half_rn(v.w));
}

__global__ void k_split_w(const float* __restrict__ wq,
                          const float* __restrict__ wk,
                          const float* __restrict__ wv,
                          const float* __restrict__ wo) {
    int gid = blockIdx.x * blockDim.x + threadIdx.x;
    if (gid >= 65536) return;
    int sect = gid >> 14;
    int i    = gid & 16383;
    const float* src = (sect == 0) ? wq : (sect == 1) ? wk
                     : (sect == 2) ? wv : wo;
    float4 v = ((const float4*)src)[i];
    __half2 a = __halves2half2(__float2half_rn(v.x), __float2half_rn(v.y));
    __half2 b = __halves2half2(__float2half_rn(v.z), __float2half_rn(v.w));
    int k = (i * 4) >> 8;
    int n = (i * 4) & 255;
    if (sect < 3) {
        __half2* d = (__half2*)&g_wqkv[(size_t)k * 768 + sect * 256 + n];
        d[0] = a; d[1] = b;
    } else {
        __half2* d = (__half2*)&g_wo[(size_t)k * 256 + n];
        d[0] = a; d[1] = b;
    }
}

__global__ void k_bm(const float* __restrict__ mask,
                     const float* __restrict__ bias_table,
                     const int* __restrict__ rel_index) {
    const int bid = blockIdx.x;
    const int w   = bid >> 3;
    const int h   = bid & 7;
    float* dst = g_bm + (size_t)bid * BMWIN;
    const float* mrow = mask + (size_t)w * (L_TOK * L_TOK);
    for (int i = threadIdx.x; i < L_TOK * L_TOK; i += blockDim.x)
        dst[(i / L_TOK) * BMROW + (i % L_TOK)] =
            bias_table[rel_index[i] * NHEAD + h] + mrow[i];
}

// ------------------------------ GEMM ----------------------------------------
// BM=128 BN=128 BK=64, 4 warps (2m x 2n), warp tile 64x64.

#define AROWH 72
#define BROWH 136
#define O_A 0
#define O_B 18432
#define S_BUF 35840
#define SMEM_BYTES (2 * S_BUF)
#define CS 136

__global__ __launch_bounds__(128, 2)
void k_hgemm(const __half* __restrict__ Ah, const __half* __restrict__ Wh,
             int ldW, float* __restrict__ Cf, int ldC, int mode)
{
    extern __shared__ char smem[];
    const uint32_t sb = smem_u32(smem);
    const int tid  = threadIdx.x;
    const int lane = tid & 31;
    const int wid  = tid >> 5;
    const int warp_m = wid & 1;
    const int warp_n = wid >> 1;
    const int rowBlock = blockIdx.y * 128;
    const int col0     = blockIdx.x * 128;

    float acc[4][8][4];
#pragma unroll
    for (int mt = 0; mt < 4; mt++)
#pragma unroll
        for (int nt = 0; nt < 8; nt++)
#pragma unroll
            for (int i = 0; i < 4; i++) acc[mt][nt][i] = 0.f;

    auto issue = [&](int c, int buf) {
        uint32_t s = sb + buf * S_BUF;
#pragma unroll
        for (int q8 = 0; q8 < 8; q8++) {
            int q   = tid + 128 * q8;
            int row = q >> 3;
            int seg = (q & 7) * 8;
            cp16(s + O_A + row * (AROWH * 2) + seg * 2,
                 Ah + (size_t)(rowBlock + row) * CH + c * 64 + seg);
        }
#pragma unroll
        for (int q8 = 0; q8 < 8; q8++) {
            int q   = tid + 128 * q8;
            int k   = q >> 4;
            int seg = (q & 15) * 8;
            cp16(s + O_B + k * (BROWH * 2) + seg * 2,
                 Wh + (size_t)(c * 64 + k) * ldW + col0 + seg);
        }
        CP_COMMIT();
    };

    const int arow_l = warp_m * 64 + (lane & 15);
    const int acol_l = (lane >> 4) * 8;
    const int brow_l = (lane & 7) + ((lane >> 3) & 1) * 8;
    const int bcol_l = warp_n * 64 + (lane >> 4) * 8;

    issue(0, 0);

#pragma unroll 1
    for (int c = 0; c < 4; c++) {
        if (c < 3) { issue(c + 1, (c + 1) & 1); CP_WAIT1(); }
        else       { CP_WAIT0(); }
        __syncthreads();

        const uint32_t s = sb + (c & 1) * S_BUF;
#pragma unroll
        for (int ks = 0; ks < 4; ks++) {
            uint32_t a[4][4], b[4][4];
            const uint32_t aoff = (acol_l + ks * 16) * 2;
#pragma unroll
            for (int mt = 0; mt < 4; mt++)
                ldsm_x4(s + O_A + (arow_l + mt * 16) * (AROWH * 2) + aoff,
                        a[mt]);
            const uint32_t brow = (brow_l + ks * 16) * (BROWH * 2);
#pragma unroll
            for (int np = 0; np < 4; np++)
                ldsm_x4_t(s + O_B + brow + (bcol_l + np * 16) * 2, b[np]);
#pragma unroll
            for (int mt = 0; mt < 4; mt++)
#pragma unroll
                for (int nt = 0; nt < 8; nt++)
                    mma16816(acc[mt][nt], a[mt], &b[nt >> 1][(nt & 1) * 2]);
        }
        __syncthreads();
    }

    // ---- epilogue via smem -> STG.128 ----
    float* cs = (float*)smem;
    const int g  = lane >> 2;
    const int tc = (lane & 3) * 2;
#pragma unroll
    for (int mt = 0; mt < 4; mt++) {
        const int r = warp_m * 64 + mt * 16 + g;
#pragma unroll
        for (int nt = 0; nt < 8; nt++) {
            const int cc = warp_n * 64 + nt * 8 + tc;
            *(float2*)&cs[r * CS + cc] =
                make_float2(acc[mt][nt][0], acc[mt][nt][1]);
            *(float2*)&cs[(r + 8) * CS + cc] =
                make_float2(acc[mt][nt][2], acc[mt][nt][3]);
        }
    }
    __syncthreads();

#pragma unroll
    for (int i = 0; i < 16; i++) {
        const int id  = tid + 128 * i;
        const int row = id >> 4;
        const int col = (id & 15) * 8;
        float4 v0 = *(float4*)&cs[row * CS + col];
        float4 v1 = *(float4*)&cs[row * CS + col + 4];
        if (mode == 0) {
            uint4 hi;
            hi.x = pack_h2(v0.x, v0.y); hi.y = pack_h2(v0.z, v0.w);
            hi.z = pack_h2(v1.x, v1.y); hi.w = pack_h2(v1.z, v1.w);
            size_t o = (size_t)(rowBlock + row) * 768 + col0 + col;
            *(uint4*)&g_qh[o] = hi;
        } else {
            size_t o = (size_t)(rowBlock + row) * ldC + col0 + col;
            *(float4*)&Cf[o]     = v0;
            *(float4*)&Cf[o + 4] = v1;
        }
    }
}

// ------------------------------ attention (HMMA) ----------------------------
// One CTA per (window, head), 4 warps. QK 1-pass, AV 1-pass.

#define KSTR 40

__global__ __launch_bounds__(128)
void attn_kernel()
{
    __shared__ __align__(16) __half sQ [64 * KSTR];
    __shared__ __align__(16) __half sKh[64 * KSTR];
    __shared__ __align__(16) __half sVh[64 * KSTR];

    const int bid = blockIdx.x;
    const int h   = bid & 7;
    const int n   = bid >> 3;
    const int tid = threadIdx.x;

    // zero V pad rows 49..63
    for (int idx = tid; idx < 60; idx += 128) {
        int r  = 49 + (idx >> 2);
        int q4 = idx & 3;
        *(int4*)(sVh + r * KSTR + q4 * 8) = make_int4(0, 0, 0, 0);
    }
    // load Q, K, V (hi planes): 3 planes x 49 rows x 4 int4
    {
        const size_t rb = (size_t)n * L_TOK * 768 + h * DK;
        for (int idx = tid; idx < 3 * 196; idx += 128) {
            int p   = idx / 196;
            int rem = idx - p * 196;
            int r   = rem >> 2;
            int q4  = rem & 3;
            const __half* src;
            __half* dst;
            switch (p) {
                case 0: src = g_qh + rb;       dst = sQ;  break;
                case 1: src = g_qh + rb + 256; dst = sKh; break;
                default: src = g_qh + rb + 512; dst = sVh; break;
            }
            *(int4*)(dst + r * KSTR + q4 * 8) =
                *(const int4*)(src + (size_t)r * 768 + q4 * 8);
        }
    }
    __syncthreads();

    const int warp = tid >> 5;
    const int lane = tid & 31;
    const int g    = lane >> 2;
    const int t    = lane & 3;

    const uint32_t bq  = smem_u32(sQ);
    const uint32_t bkh = smem_u32(sKh);
    const int aRow = warp * 16 + (lane & 15);
    const int aCol = (lane >> 4) * 8;

    uint32_t qa[2][4];
    ldsm_x4(bq + (aRow * KSTR + aCol) * 2, qa[0]);
    ldsm_x4(bq + (aRow * KSTR + aCol + 16) * 2, qa[1]);

    float c[8][4];
#pragma unroll
    for (int nt = 0; nt < 8; nt++)
#pragma unroll
        for (int i = 0; i < 4; i++) c[nt][i] = 0.f;

#pragma unroll
    for (int kt = 0; kt < 2; kt++) {
#pragma unroll
        for (int jp = 0; jp < 4; jp++) {
            uint32_t kb[4];
            ldsm_x4(bkh + ((jp * 16 + (lane & 15)) * KSTR +
                           (lane >> 4) * 8 + kt * 16) * 2, kb);
            uint32_t b0[2] = {kb[0], kb[2]};
            uint32_t b1[2] = {kb[1], kb[3]};
            mma16816(c[jp * 2],     qa[kt], b0);
            mma16816(c[jp * 2 + 1], qa[kt], b1);
        }
    }

    // ---- bias+mask direct from L2, softmax ----
    const int r0 = warp * 16 + g;
    const int r1 = r0 + 8;
    const float* bm = g_bm + (size_t)(((n & 63) << 3) | h) * BMWIN;
    const int r0e = (r0 < L_TOK ? r0 : L_TOK - 1) * BMROW;
    const int r1e = (r1 < L_TOK ? r1 : L_TOK - 1) * BMROW;
#pragma unroll
    for (int nt = 0; nt < 8; nt++) {
        const int j0 = nt * 8 + t * 2;
        if (j0 < L_TOK) {
            float2 b0 = __ldg((const float2*)&bm[r0e + j0]);
            float2 b1 = __ldg((const float2*)&bm[r1e + j0]);
            c[nt][0] += b0.x;
            c[nt][2] += b1.x;
            if (j0 + 1 < L_TOK) { c[nt][1] += b0.y; c[nt][3] += b1.y; }
            else { c[nt][1] = -3.0e38f; c[nt][3] = -3.0e38f; }
        } else {
            c[nt][0] = c[nt][1] = c[nt][2] = c[nt][3] = -3.0e38f;
        }
    }

    float mx0 = -3.0e38f, mx1 = -3.0e38f;
#pragma unroll
    for (int nt = 0; nt < 8; nt++) {
        mx0 = fmaxf(mx0, fmaxf(c[nt][0], c[nt][1]));
        mx1 = fmaxf(mx1, fmaxf(c[nt][2], c[nt][3]));
    }
    mx0 = fmaxf(mx0, __shfl_xor_sync(0xffffffffu, mx0, 1));
    mx0 = fmaxf(mx0, __shfl_xor_sync(0xffffffffu, mx0, 2));
    mx1 = fmaxf(mx1, __shfl_xor_sync(0xffffffffu, mx1, 1));
    mx1 = fmaxf(mx1, __shfl_xor_sync(0xffffffffu, mx1, 2));

    float s0 = 0.f, s1 = 0.f;
#pragma unroll
    for (int nt = 0; nt < 8; nt++) {
        c[nt][0] = __expf(c[nt][0] - mx0); s0 += c[nt][0];
        c[nt][1] = __expf(c[nt][1] - mx0); s0 += c[nt][1];
        c[nt][2] = __expf(c[nt][2] - mx1); s1 += c[nt][2];
        c[nt][3] = __expf(c[nt][3] - mx1); s1 += c[nt][3];
    }
    s0 += __shfl_xor_sync(0xffffffffu, s0, 1);
    s0 += __shfl_xor_sync(0xffffffffu, s0, 2);
    s1 += __shfl_xor_sync(0xffffffffu, s1, 1);
    s1 += __shfl_xor_sync(0xffffffffu, s1, 2);
    const float rs0 = 1.f / s0;
    const float rs1 = 1.f / s1;

    // ---- AV: single pass ----
    const uint32_t bvh = smem_u32(sVh);
    const int vRow = (lane & 7) + ((lane >> 3) & 1) * 8;
    const int vCol = (lane >> 4) * 8;

    float o[4][4];
#pragma unroll
    for (int nt = 0; nt < 4; nt++)
#pragma unroll
        for (int i = 0; i < 4; i++) o[nt][i] = 0.f;

#pragma unroll
    for (int kt = 0; kt < 4; kt++) {
        uint32_t ph[4];
#pragma unroll
        for (int q = 0; q < 2; q++) {
            const float* cc = c[2 * kt + q];
            ph[q * 2]     = pack_h2(cc[0], cc[1]);
            ph[q * 2 + 1] = pack_h2(cc[2], cc[3]);
        }
        uint32_t vh[2][4];
        const uint32_t roff = (kt * 16 + vRow) * KSTR;
        ldsm_x4_t(bvh + (roff + vCol) * 2,      vh[0]);
        ldsm_x4_t(bvh + (roff + vCol + 16) * 2, vh[1]);
#pragma unroll
        for (int nt = 0; nt < 4; nt++)
            mma16816(o[nt], ph, &vh[nt >> 1][(nt & 1) * 2]);
    }

    if (r0 < L_TOK) {
        __half* orow = g_ah + (size_t)(n * L_TOK + r0) * CH + h * DK;
#pragma unroll
        for (int nt = 0; nt < 4; nt++)
            *(__half2*)&orow[nt * 8 + t * 2] =
                __halves2half2(__float2half_rn(o[nt][0] * rs0),
                               __float2half_rn(o[nt][1] * rs0));
    }
    if (r1 < L_TOK) {
        __half* orow = g_ah + (size_t)(n * L_TOK + r1) * CH + h * DK;
#pragma unroll
        for (int nt = 0; nt < 4; nt++)
            *(__half2*)&orow[nt * 8 + t * 2] =
                __halves2half2(__float2half_rn(o[nt][2] * rs1),
                               __float2half_rn(o[nt][3] * rs1));
    }
}

// ------------------------------- launch --------------------------------------

extern "C" void kernel_launch(void* const* d_in, const int* in_sizes, int n_in,
                              void* d_out, int out_size)
{
    (void)in_sizes; (void)n_in; (void)out_size;
    const float* x    = (const float*)d_in[0];
    const float* mask = (const float*)d_in[1];
    const float* wq   = (const float*)d_in[2];
    const float* wk   = (const float*)d_in[3];
    const float* wv   = (const float*)d_in[4];
    const float* wo   = (const float*)d_in[5];
    const float* bias = (const float*)d_in[6];
    const int*   rel  = (const int*)d_in[7];
    float* out = (float*)d_out;

    static __half *xh = nullptr, *ah = nullptr, *wqkv = nullptr, *woh = nullptr;
    if (!xh) {
        cudaGetSymbolAddress((void**)&xh,   g_xh);
        cudaGetSymbolAddress((void**)&ah,   g_ah);
        cudaGetSymbolAddress((void**)&wqkv, g_wqkv);
        cudaGetSymbolAddress((void**)&woh,  g_wo);
        cudaFuncSetAttribute(k_hgemm,
                             cudaFuncAttributeMaxDynamicSharedMemorySize,
                             SMEM_BYTES);
    }

    k_split_x<<<(M_ROWS * CH / 4 + 255) / 256, 256>>>(x);
    k_split_w<<<256, 256>>>(wq, wk, wv, wo);
    k_bm<<<512, 256>>>(mask, bias, rel);
    k_hgemm<<<dim3(6, M_ROWS / 128), 128, SMEM_BYTES>>>(xh, wqkv, 768,
                                                        nullptr, 768, 0);
    attn_kernel<<<N_WIN * NHEAD, 128>>>();
    k_hgemm<<<dim3(2, M_ROWS / 128), 128, SMEM_BYTES>>>(ah, woh, 256,
                                                        out, 256, 1);
}